// round 5
// baseline (speedup 1.0000x reference)
#include <cuda_runtime.h>
#include <math.h>

#define HOPS  2
#define BB    2048
#define MM    64
#define DD    16
#define NREL  32
#define QSTR  17      // smem q row stride (floats)

// Precomputed q[b][r][j] = sum_i item_b[i] * R[r][i][j]   (4 MB scratch)
__device__ float q_scratch[BB * NREL * DD];

// ---------------------------------------------------------------------------
// Kernel 1: q precompute. 4 batches per block, R loads amortized 4x.
// ---------------------------------------------------------------------------
__global__ __launch_bounds__(128, 8)
void q_kernel(const int*   __restrict__ items,
              const float* __restrict__ ent_emb,
              const float* __restrict__ rel_emb)
{
    const int b0  = blockIdx.x * 4;
    const int tid = threadIdx.x;

    __shared__ float s_item[4][DD];
    if (tid < 64) {
        const int w  = tid >> 4;
        const int it = __ldg(items + b0 + w);
        s_item[w][tid & 15] = __ldg(ent_emb + (size_t)it * DD + (tid & 15));
    }
    __syncthreads();

    const int r  = tid >> 2;
    const int j0 = (tid & 3) * 4;
    const float4* Rp = (const float4*)(rel_emb + (size_t)r * DD * DD + j0);

    float4 a0 = make_float4(0.f,0.f,0.f,0.f), a1 = a0, a2 = a0, a3 = a0;
    #pragma unroll
    for (int i = 0; i < DD; i++) {
        const float4 Rv = __ldg(Rp + i * 4);
        const float i0 = s_item[0][i], i1 = s_item[1][i];
        const float i2 = s_item[2][i], i3 = s_item[3][i];
        a0.x = fmaf(i0, Rv.x, a0.x); a0.y = fmaf(i0, Rv.y, a0.y);
        a0.z = fmaf(i0, Rv.z, a0.z); a0.w = fmaf(i0, Rv.w, a0.w);
        a1.x = fmaf(i1, Rv.x, a1.x); a1.y = fmaf(i1, Rv.y, a1.y);
        a1.z = fmaf(i1, Rv.z, a1.z); a1.w = fmaf(i1, Rv.w, a1.w);
        a2.x = fmaf(i2, Rv.x, a2.x); a2.y = fmaf(i2, Rv.y, a2.y);
        a2.z = fmaf(i2, Rv.z, a2.z); a2.w = fmaf(i2, Rv.w, a2.w);
        a3.x = fmaf(i3, Rv.x, a3.x); a3.y = fmaf(i3, Rv.y, a3.y);
        a3.z = fmaf(i3, Rv.z, a3.z); a3.w = fmaf(i3, Rv.w, a3.w);
    }
    float4* qv = (float4*)q_scratch;
    qv[(size_t)(b0 + 0) * 128 + tid] = a0;
    qv[(size_t)(b0 + 1) * 128 + tid] = a1;
    qv[(size_t)(b0 + 2) * 128 + tid] = a2;
    qv[(size_t)(b0 + 3) * 128 + tid] = a3;
}

// ---------------------------------------------------------------------------
// Kernel 2: main. 1 batch/block, 128 threads, grid 2048.
// Quad (4 lanes) owns one (h,m) slot per pass; lane j loads float4 quarter j.
// Pass p: hop = p>>1, m = (p&1)*32 + row.
// ---------------------------------------------------------------------------
__global__ __launch_bounds__(128)
void ripplenet_kernel(const int*   __restrict__ items,
                      const int*   __restrict__ heads,
                      const int*   __restrict__ relations,
                      const int*   __restrict__ tails,
                      const float* __restrict__ ent_emb,
                      float*       __restrict__ out)
{
    const int b    = blockIdx.x;
    const int tid  = threadIdx.x;
    const int lane = tid & 31;
    const int wid  = tid >> 5;        // 0..3
    const int j    = tid & 3;         // float4 quarter owned by this lane
    const int row  = tid >> 2;        // 0..31

    __shared__ float s_item[DD];
    __shared__ float s_q[NREL * QSTR];
    __shared__ float s_red[4][4][2];  // [pass][warp]{E,S}

    // ---- indices: pass p -> (hop = p>>1, m = (p&1)*32 + row) ----
    int he[4], re[4], te[4];
    #pragma unroll
    for (int p = 0; p < 4; p++) {
        const int h   = p >> 1;
        const int m   = (p & 1) * 32 + row;
        const int idx = h * (BB * MM) + b * MM + m;
        he[p] = __ldg(heads + idx);
        re[p] = __ldg(relations + idx);
        te[p] = __ldg(tails + idx);
    }

    // ---- issue ALL gathers: lane j takes quarter j of each row ----
    float4 hq[4], tq[4];
    #pragma unroll
    for (int p = 0; p < 4; p++) {
        hq[p] = __ldg((const float4*)(ent_emb + (size_t)he[p] * DD) + j);
        tq[p] = __ldg((const float4*)(ent_emb + (size_t)te[p] * DD) + j);
    }

    // ---- item embedding -> smem ----
    if (tid < DD) {
        const int it = __ldg(items + b);
        s_item[tid] = __ldg(ent_emb + (size_t)it * DD + tid);
    }

    // ---- q tile (precomputed): 512 floats, 1 float4/thread, restrided ----
    {
        const int off = tid * 4;
        const float4 v = *(const float4*)(q_scratch + (size_t)b * (NREL * DD) + off);
        float* dst = &s_q[(off >> 4) * QSTR + (off & 15)];
        dst[0] = v.x; dst[1] = v.y; dst[2] = v.z; dst[3] = v.w;
    }
    __syncthreads();

    // ---- consume: partial dots over this lane's 4 dims, quad-reduce ----
    #pragma unroll
    for (int p = 0; p < 4; p++) {
        const float* qr = &s_q[re[p] * QSTR + j * 4];
        const float* it = &s_item[j * 4];

        float pd = 0.f, td = 0.f;
        pd = fmaf(qr[0], hq[p].x, pd); pd = fmaf(qr[1], hq[p].y, pd);
        pd = fmaf(qr[2], hq[p].z, pd); pd = fmaf(qr[3], hq[p].w, pd);
        td = fmaf(it[0], tq[p].x, td); td = fmaf(it[1], tq[p].y, td);
        td = fmaf(it[2], tq[p].z, td); td = fmaf(it[3], tq[p].w, td);

        // quad butterfly -> full logit / tdot in all 4 lanes of the quad
        pd += __shfl_xor_sync(0xffffffffu, pd, 1);
        pd += __shfl_xor_sync(0xffffffffu, pd, 2);
        td += __shfl_xor_sync(0xffffffffu, td, 1);
        td += __shfl_xor_sync(0xffffffffu, td, 2);

        // logits are O(1): exp safe without max-subtraction
        float E = __expf(pd);
        float S = E * td;

        // warp butterfly over quads: each slot counted 4x -> cancels in S/E
        #pragma unroll
        for (int o = 4; o < 32; o <<= 1) {
            E += __shfl_xor_sync(0xffffffffu, E, o);
            S += __shfl_xor_sync(0xffffffffu, S, o);
        }
        if (lane == 0) { s_red[p][wid][0] = E; s_red[p][wid][1] = S; }
    }
    __syncthreads();

    // ---- finalize: hop h uses passes 2h, 2h+1 ----
    if (tid == 0) {
        float u = 0.f;
        #pragma unroll
        for (int h = 0; h < 2; h++) {
            float E = 0.f, S = 0.f;
            #pragma unroll
            for (int p = 2 * h; p < 2 * h + 2; p++)
                #pragma unroll
                for (int w = 0; w < 4; w++) {
                    E += s_red[p][w][0];
                    S += s_red[p][w][1];
                }
            u += S / E;
        }
        out[b] = 1.f / (1.f + __expf(-u));
    }
}

extern "C" void kernel_launch(void* const* d_in, const int* in_sizes, int n_in,
                              void* d_out, int out_size)
{
    const int*   items     = (const int*)  d_in[0];
    const int*   heads     = (const int*)  d_in[1];
    const int*   relations = (const int*)  d_in[2];
    const int*   tails     = (const int*)  d_in[3];
    const float* ent_emb   = (const float*)d_in[4];
    const float* rel_emb   = (const float*)d_in[5];
    float* out = (float*)d_out;

    q_kernel<<<BB / 4, 128>>>(items, ent_emb, rel_emb);
    ripplenet_kernel<<<BB, 128>>>(items, heads, relations, tails, ent_emb, out);
}

// round 6
// speedup vs baseline: 1.0631x; 1.0631x over previous
#include <cuda_runtime.h>
#include <math.h>

#define HOPS  2
#define BB    2048
#define MM    64
#define DD    16
#define NREL  32
#define QSTR  17      // smem q row stride (floats)

// Precomputed q[b][r][j] = sum_i item_b[i] * R[r][i][j]   (4 MB scratch)
__device__ float q_scratch[BB * NREL * DD];

// ---------------------------------------------------------------------------
// Kernel 1: q precompute. 4 batches per block, R loads amortized 4x.
// Triggers programmatic launch of the main kernel after its stores.
// ---------------------------------------------------------------------------
__global__ __launch_bounds__(128, 8)
void q_kernel(const int*   __restrict__ items,
              const float* __restrict__ ent_emb,
              const float* __restrict__ rel_emb)
{
    const int b0  = blockIdx.x * 4;
    const int tid = threadIdx.x;

    __shared__ float s_item[4][DD];
    if (tid < 64) {
        const int w  = tid >> 4;
        const int it = __ldg(items + b0 + w);
        s_item[w][tid & 15] = __ldg(ent_emb + (size_t)it * DD + (tid & 15));
    }
    __syncthreads();

    const int r  = tid >> 2;
    const int j0 = (tid & 3) * 4;
    const float4* Rp = (const float4*)(rel_emb + (size_t)r * DD * DD + j0);

    float4 a0 = make_float4(0.f,0.f,0.f,0.f), a1 = a0, a2 = a0, a3 = a0;
    #pragma unroll
    for (int i = 0; i < DD; i++) {
        const float4 Rv = __ldg(Rp + i * 4);
        const float i0 = s_item[0][i], i1 = s_item[1][i];
        const float i2 = s_item[2][i], i3 = s_item[3][i];
        a0.x = fmaf(i0, Rv.x, a0.x); a0.y = fmaf(i0, Rv.y, a0.y);
        a0.z = fmaf(i0, Rv.z, a0.z); a0.w = fmaf(i0, Rv.w, a0.w);
        a1.x = fmaf(i1, Rv.x, a1.x); a1.y = fmaf(i1, Rv.y, a1.y);
        a1.z = fmaf(i1, Rv.z, a1.z); a1.w = fmaf(i1, Rv.w, a1.w);
        a2.x = fmaf(i2, Rv.x, a2.x); a2.y = fmaf(i2, Rv.y, a2.y);
        a2.z = fmaf(i2, Rv.z, a2.z); a2.w = fmaf(i2, Rv.w, a2.w);
        a3.x = fmaf(i3, Rv.x, a3.x); a3.y = fmaf(i3, Rv.y, a3.y);
        a3.z = fmaf(i3, Rv.z, a3.z); a3.w = fmaf(i3, Rv.w, a3.w);
    }
    float4* qv = (float4*)q_scratch;
    qv[(size_t)(b0 + 0) * 128 + tid] = a0;
    qv[(size_t)(b0 + 1) * 128 + tid] = a1;
    qv[(size_t)(b0 + 2) * 128 + tid] = a2;
    qv[(size_t)(b0 + 3) * 128 + tid] = a3;

    // allow the dependent (main) kernel's blocks to launch; its
    // cudaGridDependencySynchronize() guarantees visibility of the stores above.
    cudaTriggerProgrammaticLaunchCompletion();
}

// ---------------------------------------------------------------------------
// Kernel 2: main. 1 batch/block, 128 threads, grid 2048, PDL-overlapped.
// Quad (4 lanes) owns one (h,m) slot per pass; lane j loads float4 quarter j.
// Pass p: hop = p>>1, m = (p&1)*32 + row.
// ---------------------------------------------------------------------------
__global__ __launch_bounds__(128)
void ripplenet_kernel(const int*   __restrict__ items,
                      const int*   __restrict__ heads,
                      const int*   __restrict__ relations,
                      const int*   __restrict__ tails,
                      const float* __restrict__ ent_emb,
                      float*       __restrict__ out)
{
    const int b    = blockIdx.x;
    const int tid  = threadIdx.x;
    const int lane = tid & 31;
    const int wid  = tid >> 5;        // 0..3
    const int j    = tid & 3;         // float4 quarter owned by this lane
    const int row  = tid >> 2;        // 0..31

    __shared__ float s_item[DD];
    __shared__ float s_q[NREL * QSTR];
    __shared__ float s_red[4][4][2];  // [pass][warp]{E,S}

    // ---- front section: fully independent of q_scratch, overlaps q_kernel ----
    int he[4], re[4], te[4];
    #pragma unroll
    for (int p = 0; p < 4; p++) {
        const int h   = p >> 1;
        const int m   = (p & 1) * 32 + row;
        const int idx = h * (BB * MM) + b * MM + m;
        he[p] = __ldg(heads + idx);
        re[p] = __ldg(relations + idx);
        te[p] = __ldg(tails + idx);
    }

    float4 hq[4], tq[4];
    #pragma unroll
    for (int p = 0; p < 4; p++) {
        hq[p] = __ldg((const float4*)(ent_emb + (size_t)he[p] * DD) + j);
        tq[p] = __ldg((const float4*)(ent_emb + (size_t)te[p] * DD) + j);
    }

    if (tid < DD) {
        const int it = __ldg(items + b);
        s_item[tid] = __ldg(ent_emb + (size_t)it * DD + tid);
    }

    // ---- wait for q_kernel's stores to be visible, then load q tile ----
    cudaGridDependencySynchronize();
    {
        const int off = tid * 4;
        const float4 v = *(const float4*)(q_scratch + (size_t)b * (NREL * DD) + off);
        float* dst = &s_q[(off >> 4) * QSTR + (off & 15)];
        dst[0] = v.x; dst[1] = v.y; dst[2] = v.z; dst[3] = v.w;
    }
    __syncthreads();

    // ---- consume: partial dots over this lane's 4 dims, quad-reduce ----
    #pragma unroll
    for (int p = 0; p < 4; p++) {
        const float* qr = &s_q[re[p] * QSTR + j * 4];
        const float* it = &s_item[j * 4];

        float pd = 0.f, td = 0.f;
        pd = fmaf(qr[0], hq[p].x, pd); pd = fmaf(qr[1], hq[p].y, pd);
        pd = fmaf(qr[2], hq[p].z, pd); pd = fmaf(qr[3], hq[p].w, pd);
        td = fmaf(it[0], tq[p].x, td); td = fmaf(it[1], tq[p].y, td);
        td = fmaf(it[2], tq[p].z, td); td = fmaf(it[3], tq[p].w, td);

        // quad butterfly -> full logit / tdot in all 4 lanes of the quad
        pd += __shfl_xor_sync(0xffffffffu, pd, 1);
        pd += __shfl_xor_sync(0xffffffffu, pd, 2);
        td += __shfl_xor_sync(0xffffffffu, td, 1);
        td += __shfl_xor_sync(0xffffffffu, td, 2);

        // logits are O(1): exp safe without max-subtraction
        float E = __expf(pd);
        float S = E * td;

        // warp butterfly over quads: each slot counted 4x -> cancels in S/E
        #pragma unroll
        for (int o = 4; o < 32; o <<= 1) {
            E += __shfl_xor_sync(0xffffffffu, E, o);
            S += __shfl_xor_sync(0xffffffffu, S, o);
        }
        if (lane == 0) { s_red[p][wid][0] = E; s_red[p][wid][1] = S; }
    }
    __syncthreads();

    // ---- finalize: hop h uses passes 2h, 2h+1 ----
    if (tid == 0) {
        float u = 0.f;
        #pragma unroll
        for (int h = 0; h < 2; h++) {
            float E = 0.f, S = 0.f;
            #pragma unroll
            for (int p = 2 * h; p < 2 * h + 2; p++)
                #pragma unroll
                for (int w = 0; w < 4; w++) {
                    E += s_red[p][w][0];
                    S += s_red[p][w][1];
                }
            u += S / E;
        }
        out[b] = 1.f / (1.f + __expf(-u));
    }
}

extern "C" void kernel_launch(void* const* d_in, const int* in_sizes, int n_in,
                              void* d_out, int out_size)
{
    const int*   items     = (const int*)  d_in[0];
    const int*   heads     = (const int*)  d_in[1];
    const int*   relations = (const int*)  d_in[2];
    const int*   tails     = (const int*)  d_in[3];
    const float* ent_emb   = (const float*)d_in[4];
    const float* rel_emb   = (const float*)d_in[5];
    float* out = (float*)d_out;

    q_kernel<<<BB / 4, 128>>>(items, ent_emb, rel_emb);

    // Main kernel with programmatic dependent launch: its front section
    // (index loads + embedding gathers) overlaps the tail of q_kernel.
    cudaLaunchConfig_t cfg = {};
    cfg.gridDim  = dim3(BB, 1, 1);
    cfg.blockDim = dim3(128, 1, 1);
    cfg.dynamicSmemBytes = 0;
    cudaLaunchAttribute attrs[1];
    attrs[0].id = cudaLaunchAttributeProgrammaticStreamSerialization;
    attrs[0].val.programmaticStreamSerializationAllowed = 1;
    cfg.attrs = attrs;
    cfg.numAttrs = 1;
    cudaLaunchKernelEx(&cfg, ripplenet_kernel,
                       items, heads, relations, tails, ent_emb, out);
}